// round 8
// baseline (speedup 1.0000x reference)
#include <cuda_runtime.h>
#include <cuda_bf16.h>
#include <cstdint>

// Problem constants
#define NGR 4
#define GF 256
#define DIN 834
#define SS 1568
#define NB 16
#define TOT 160
#define IDIM 1024
#define NMAX 16

// padded dims for MMA
#define CPAD 896            // K padded (28 chunks of 32)
#define SPAD 1664           // s padded (26 tiles of 64)
#define KCHUNKS 28
#define STILES 26           // N tiles of 64
#define MTILES 2            // 256 f / 128

// smem layout for ctx_mma_k: 80B row stride; A 128 rows, B 64 rows per tile
#define RS 80
#define AT_B (128 * RS)     // 10240
#define BT_B (64 * RS)      // 5120
#define AH_OFF 0
#define AL_OFF (AT_B)
#define BH_OFF (2 * AT_B)
#define BL_OFF (2 * AT_B + BT_B)
#define STAGE_B (2 * AT_B + 2 * BT_B)   // 30720
#define SMEM_DYN (2 * STAGE_B)          // 61440

#define KSPLIT 4

// ---------------- scratch (static device globals) --------------------------
__device__ float g_emb[TOT * NGR * GF];
__device__ float g_embP[KSPLIT * TOT * NGR * GF];  // split-K partials
__device__ float g_ctx[NB * NGR * GF * SS];        // [z][f][s]
__device__ float g_adj[NB * NGR * NMAX * SS];
__device__ float g_flat[TOT * NGR * GF];
__device__ int   g_off[NB];
__device__ int   g_cnt[NB];
__device__ __nv_bfloat16 g_fmT_hi[(long long)NB * SPAD * CPAD];  // [b][s][c]
__device__ __nv_bfloat16 g_fmT_lo[(long long)NB * SPAD * CPAD];
__device__ __nv_bfloat16 g_w_hi[NGR * GF * CPAD];                // [g][f][c]
__device__ __nv_bfloat16 g_w_lo[NGR * GF * CPAD];

// ---------------- PTX helpers (baseline ISA only) ---------------------------
__device__ __forceinline__ uint32_t smem_u32(const void* p) {
    uint32_t a;
    asm("{ .reg .u64 t; cvta.to.shared.u64 t, %1; cvt.u32.u64 %0, t; }"
        : "=r"(a) : "l"(p));
    return a;
}
__device__ __forceinline__ void cp16(uint32_t dst, const void* src) {
    asm volatile("cp.async.cg.shared.global [%0], [%1], 16;"
                 :: "r"(dst), "l"(src) : "memory");
}
__device__ __forceinline__ void cp_commit() {
    asm volatile("cp.async.commit_group;" ::: "memory");
}
template <int N>
__device__ __forceinline__ void cp_wait() {
    asm volatile("cp.async.wait_group %0;" :: "n"(N) : "memory");
}
__device__ __forceinline__ void ldsm4(uint32_t& r0, uint32_t& r1, uint32_t& r2,
                                      uint32_t& r3, uint32_t a) {
    asm volatile("ldmatrix.sync.aligned.m8n8.x4.shared.b16 {%0,%1,%2,%3}, [%4];"
                 : "=r"(r0), "=r"(r1), "=r"(r2), "=r"(r3) : "r"(a));
}
__device__ __forceinline__ void mma_bf16(float* c, const uint32_t* a,
                                         uint32_t b0, uint32_t b1) {
    asm volatile(
        "mma.sync.aligned.m16n8k16.row.col.f32.bf16.bf16.f32 "
        "{%0,%1,%2,%3}, {%4,%5,%6,%7}, {%8,%9}, {%0,%1,%2,%3};"
        : "+f"(c[0]), "+f"(c[1]), "+f"(c[2]), "+f"(c[3])
        : "r"(a[0]), "r"(a[1]), "r"(a[2]), "r"(a[3]), "r"(b0), "r"(b1));
}

// ---------------- K0: ragged bookkeeping ------------------------------------
__global__ void init_offsets_k(const void* __restrict__ counts) {
    if (threadIdx.x == 0 && blockIdx.x == 0) {
        const int* c32 = (const int*)counts;
        const long long* c64 = (const long long*)counts;
        long long s = 0;
        bool ok32 = true;
        for (int b = 0; b < NB; b++) {
            int v = c32[b];
            if (v < 0 || v > NMAX) ok32 = false;
            s += v;
        }
        if (s != TOT) ok32 = false;
        int acc = 0;
        for (int b = 0; b < NB; b++) {
            int c = ok32 ? c32[b] : (int)c64[b];
            if (c < 0) c = 0;
            if (c > NMAX) c = NMAX;
            g_off[b] = acc;
            g_cnt[b] = c;
            acc += c;
        }
    }
}

// ---------------- prep: split W_c into bf16 hi/lo, pad K --------------------
__global__ void __launch_bounds__(256) split_w_k(const float* __restrict__ Wc) {
    int id = blockIdx.x * 256 + threadIdx.x;
    if (id >= NGR * GF * CPAD) return;
    int cp = id % CPAD;
    int fg = id / CPAD;
    float v = (cp < DIN) ? Wc[(long long)fg * DIN + cp] : 0.f;
    __nv_bfloat16 h = __float2bfloat16(v);
    __nv_bfloat16 l = __float2bfloat16(v - __bfloat162float(h));
    g_w_hi[id] = h;
    g_w_lo[id] = l;
}

// ---------------- prep: transpose+split fm [b][c][s] -> [b][s][c] -----------
__global__ void __launch_bounds__(256) split_fm_k(const float* __restrict__ fm) {
    __shared__ float tile[32][33];
    int b = blockIdx.z;
    int s0 = blockIdx.x * 32, c0 = blockIdx.y * 32;
    int tx = threadIdx.x, ty = threadIdx.y;     // (32, 8)

#pragma unroll
    for (int i = 0; i < 4; i++) {
        int c = c0 + ty + i * 8;
        int s = s0 + tx;
        float v = 0.f;
        if (c < DIN && s < SS) v = fm[((long long)b * DIN + c) * SS + s];
        tile[ty + i * 8][tx] = v;
    }
    __syncthreads();
#pragma unroll
    for (int i = 0; i < 4; i++) {
        int s = s0 + ty + i * 8;
        int c = c0 + tx;
        float v = tile[tx][ty + i * 8];
        __nv_bfloat16 h = __float2bfloat16(v);
        __nv_bfloat16 l = __float2bfloat16(v - __bfloat162float(h));
        long long o = ((long long)b * SPAD + s) * CPAD + c;
        g_fmT_hi[o] = h;
        g_fmT_lo[o] = l;
    }
}

// ---------------- K2: ctx via mma.sync bf16 (3-term split), 3 CTA/SM --------
// CTA tile: M(f)=128, N(s)=64, K chunk=32, 2-stage cp.async pipeline.
__global__ void __launch_bounds__(256, 3)
ctx_mma_k(const float* __restrict__ bc) {
    extern __shared__ __align__(16) char sm[];

    int tid = threadIdx.x;
    int lane = tid & 31, wid = tid >> 5;
    int bx = blockIdx.x;
    int stile = bx % STILES;
    int mtile = bx / STILES;
    int z = blockIdx.y;
    int b = z >> 2, g = z & 3;

    uint32_t sb = smem_u32(sm);

    const char* Ahc = (const char*)(g_w_hi + ((long long)g * GF + mtile * 128) * CPAD);
    const char* Alc = (const char*)(g_w_lo + ((long long)g * GF + mtile * 128) * CPAD);
    const char* Bhc = (const char*)(g_fmT_hi + ((long long)b * SPAD + stile * 64) * CPAD);
    const char* Blc = (const char*)(g_fmT_lo + ((long long)b * SPAD + stile * 64) * CPAD);

    // load slots: A tiles 512 x 16B (2 per thread), B tiles 256 x 16B (1 each)
    int idA0 = tid, idA1 = tid + 256;
    int rA0 = idA0 >> 2, cA0 = idA0 & 3;
    int rA1 = idA1 >> 2, cA1 = idA1 & 3;
    uint32_t dA0 = rA0 * RS + cA0 * 16;
    uint32_t dA1 = rA1 * RS + cA1 * 16;
    long long sA0 = (long long)rA0 * (CPAD * 2) + cA0 * 16;
    long long sA1 = (long long)rA1 * (CPAD * 2) + cA1 * 16;
    int rB = tid >> 2, cB = tid & 3;
    uint32_t dB = rB * RS + cB * 16;
    long long sB = (long long)rB * (CPAD * 2) + cB * 16;

    // warp tile: 4M x 2N -> M=32, N=32
    int warpM = wid & 3, warpN = wid >> 2;
    int m0w = warpM * 32;
    int n0w = warpN * 32;

    uint32_t aOff[2], bOff[2];
#pragma unroll
    for (int i = 0; i < 2; i++)
        aOff[i] = (m0w + i * 16 + (lane & 15)) * RS + (lane >> 4) * 16;
#pragma unroll
    for (int jj = 0; jj < 2; jj++)
        bOff[jj] = (n0w + jj * 16 + (lane & 15)) * RS + (lane >> 4) * 16;

    float acc[2][4][4];
#pragma unroll
    for (int i = 0; i < 2; i++)
#pragma unroll
        for (int j = 0; j < 4; j++)
#pragma unroll
            for (int q = 0; q < 4; q++) acc[i][j][q] = 0.f;

    {   // prologue: stage 0
        cp16(sb + AH_OFF + dA0, Ahc + sA0);
        cp16(sb + AH_OFF + dA1, Ahc + sA1);
        cp16(sb + AL_OFF + dA0, Alc + sA0);
        cp16(sb + AL_OFF + dA1, Alc + sA1);
        cp16(sb + BH_OFF + dB, Bhc + sB);
        cp16(sb + BL_OFF + dB, Blc + sB);
        cp_commit();
    }

    for (int chunk = 0; chunk < KCHUNKS; chunk++) {
        uint32_t bo = (chunk & 1) ? STAGE_B : 0;
        if (chunk + 1 < KCHUNKS) {
            long long cs = (long long)(chunk + 1) * 64;
            uint32_t nbo = ((chunk + 1) & 1) ? STAGE_B : 0;
            cp16(sb + nbo + AH_OFF + dA0, Ahc + sA0 + cs);
            cp16(sb + nbo + AH_OFF + dA1, Ahc + sA1 + cs);
            cp16(sb + nbo + AL_OFF + dA0, Alc + sA0 + cs);
            cp16(sb + nbo + AL_OFF + dA1, Alc + sA1 + cs);
            cp16(sb + nbo + BH_OFF + dB, Bhc + sB + cs);
            cp16(sb + nbo + BL_OFF + dB, Blc + sB + cs);
            cp_commit();
            cp_wait<1>();
        } else {
            cp_wait<0>();
        }
        __syncthreads();

#pragma unroll
        for (int ks = 0; ks < 2; ks++) {
            uint32_t kb = ks * 32;
            uint32_t ah[2][4], al[2][4];
#pragma unroll
            for (int i = 0; i < 2; i++) {
                ldsm4(ah[i][0], ah[i][1], ah[i][2], ah[i][3],
                      sb + bo + AH_OFF + aOff[i] + kb);
                ldsm4(al[i][0], al[i][1], al[i][2], al[i][3],
                      sb + bo + AL_OFF + aOff[i] + kb);
            }
#pragma unroll
            for (int jj = 0; jj < 2; jj++) {
                uint32_t h0, h1, h2, h3, l0, l1, l2, l3;
                ldsm4(h0, h1, h2, h3, sb + bo + BH_OFF + bOff[jj] + kb);
                ldsm4(l0, l1, l2, l3, sb + bo + BL_OFF + bOff[jj] + kb);
                int j0 = 2 * jj, j1 = 2 * jj + 1;
                // 4 independent accumulators between same-acc reuse
                mma_bf16(acc[0][j0], ah[0], h0, h2);
                mma_bf16(acc[0][j1], ah[0], h1, h3);
                mma_bf16(acc[1][j0], ah[1], h0, h2);
                mma_bf16(acc[1][j1], ah[1], h1, h3);
                mma_bf16(acc[0][j0], ah[0], l0, l2);
                mma_bf16(acc[0][j1], ah[0], l1, l3);
                mma_bf16(acc[1][j0], ah[1], l0, l2);
                mma_bf16(acc[1][j1], ah[1], l1, l3);
                mma_bf16(acc[0][j0], al[0], h0, h2);
                mma_bf16(acc[0][j1], al[0], h1, h3);
                mma_bf16(acc[1][j0], al[1], h0, h2);
                mma_bf16(acc[1][j1], al[1], h1, h3);
            }
        }
        __syncthreads();
    }

    float* Cz = g_ctx + (long long)z * GF * SS;
#pragma unroll
    for (int i = 0; i < 2; i++) {
        int f0 = mtile * 128 + m0w + i * 16 + (lane >> 2);
        float bias0 = bc[g * GF + f0];
        float bias1 = bc[g * GF + f0 + 8];
#pragma unroll
        for (int j = 0; j < 4; j++) {
            int s0 = stile * 64 + n0w + j * 8 + 2 * (lane & 3);
            if (s0 < SS) {
                float2 v0 = make_float2(acc[i][j][0] + bias0, acc[i][j][1] + bias0);
                float2 v1 = make_float2(acc[i][j][2] + bias1, acc[i][j][3] + bias1);
                *(float2*)(Cz + (long long)f0 * SS + s0) = v0;
                *(float2*)(Cz + (long long)(f0 + 8) * SS + s0) = v1;
            }
        }
    }
}

// ---------------- emb split-K partial GEMM ----------------------------------
__global__ void __launch_bounds__(256) emb_part_k(
    const float* __restrict__ A, const float* __restrict__ Bm)
{
    int z = blockIdx.z;
    int kbase = z * (IDIM / KSPLIT);

    __shared__ __align__(16) float As[32][33];
    __shared__ __align__(16) float Bs[32][65];

    int tid = threadIdx.x;
    int m0 = blockIdx.x * 32;
    int n0 = blockIdx.y * 64;
    int tx = tid % 64;
    int ty = tid / 64;

    float acc[8];
#pragma unroll
    for (int i = 0; i < 8; i++) acc[i] = 0.f;

    for (int k0 = kbase; k0 < kbase + IDIM / KSPLIT; k0 += 32) {
#pragma unroll
        for (int t = 0; t < 4; t++) {
            int lin = tid + 256 * t;
            int k = lin & 31, m = lin >> 5;
            As[k][m] = A[(m0 + m) * IDIM + k0 + k];
        }
#pragma unroll
        for (int t = 0; t < 8; t++) {
            int lin = tid + 256 * t;
            int k = lin & 31, n = lin >> 5;
            Bs[k][n] = Bm[(n0 + n) * IDIM + k0 + k];
        }
        __syncthreads();
#pragma unroll
        for (int k = 0; k < 32; k++) {
            float bv = Bs[k][tx];
#pragma unroll
            for (int i = 0; i < 8; i++)
                acc[i] += As[k][ty + 4 * i] * bv;
        }
        __syncthreads();
    }

    float* P = g_embP + (long long)z * TOT * NGR * GF;
#pragma unroll
    for (int i = 0; i < 8; i++) {
        int m = m0 + ty + 4 * i;
        P[m * (NGR * GF) + n0 + tx] = acc[i];
    }
}

__global__ void __launch_bounds__(256) emb_reduce_k(const float* __restrict__ ba) {
    int id = blockIdx.x * 256 + threadIdx.x;
    if (id >= TOT * NGR * GF) return;
    float v = ba[id & (NGR * GF - 1)];
#pragma unroll
    for (int z = 0; z < KSPLIT; z++)
        v += g_embP[z * (TOT * NGR * GF) + id];
    g_emb[id] = v;
}

// ---------------- generic GEMM (head): C = A * B^T, relu --------------------
__global__ void __launch_bounds__(256) gemm_nt_k(
    const float* __restrict__ A, int lda, long long aZ,
    const float* __restrict__ Bm, int ldb, long long bZ,
    const float* __restrict__ bias,
    float* __restrict__ C, int ldc, long long cZ,
    int K, int doRelu)
{
    int z = blockIdx.z;
    A  += (long long)z * aZ;
    Bm += (long long)z * bZ;
    C  += (long long)z * cZ;

    __shared__ __align__(16) float As[32][33];
    __shared__ __align__(16) float Bs[32][65];

    int tid = threadIdx.x;
    int m0 = blockIdx.x * 32;
    int n0 = blockIdx.y * 64;
    int tx = tid % 64;
    int ty = tid / 64;

    float acc[8];
#pragma unroll
    for (int i = 0; i < 8; i++) acc[i] = 0.f;

    for (int k0 = 0; k0 < K; k0 += 32) {
#pragma unroll
        for (int t = 0; t < 4; t++) {
            int lin = tid + 256 * t;
            int k = lin & 31, m = lin >> 5;
            As[k][m] = A[(m0 + m) * (long long)lda + k0 + k];
        }
#pragma unroll
        for (int t = 0; t < 8; t++) {
            int lin = tid + 256 * t;
            int k = lin & 31, n = lin >> 5;
            Bs[k][n] = Bm[(n0 + n) * (long long)ldb + k0 + k];
        }
        __syncthreads();
#pragma unroll
        for (int k = 0; k < 32; k++) {
            float bv = Bs[k][tx];
#pragma unroll
            for (int i = 0; i < 8; i++)
                acc[i] += As[k][ty + 4 * i] * bv;
        }
        __syncthreads();
    }

    float bb = bias ? bias[n0 + tx] : 0.f;
#pragma unroll
    for (int i = 0; i < 8; i++) {
        int m = m0 + ty + 4 * i;
        float v = acc[i] + bb;
        if (doRelu) v = fmaxf(v, 0.f);
        C[m * (long long)ldc + n0 + tx] = v;
    }
}

// ---------------- K3: adj logits (2 s-columns per thread) -------------------
__global__ void __launch_bounds__(256) adj_logits_k() {
    int g = blockIdx.y, b = blockIdx.z;
    __shared__ __align__(16) float a_s[GF * NMAX];   // [f][n]
    int tid = threadIdx.x;
    int cnt = g_cnt[b], off = g_off[b];

    for (int idx = tid; idx < GF * NMAX; idx += 256) {
        int n = idx >> 8, f = idx & 255;
        float v = 0.f;
        if (n < cnt) v = g_emb[(off + n) * (NGR * GF) + g * GF + f];
        a_s[f * NMAX + n] = v;
    }
    __syncthreads();

    int s0 = blockIdx.x * 512 + tid;
    int s1 = s0 + 256;
    if (s0 >= SS) return;
    bool ok1 = (s1 < SS);
    int s1c = ok1 ? s1 : s0;

    const float* ctxp = g_ctx + ((long long)(b * NGR + g)) * GF * SS;
    float acc0[NMAX], acc1[NMAX];
#pragma unroll
    for (int n = 0; n < NMAX; n++) { acc0[n] = 0.f; acc1[n] = 0.f; }

    const float4* ap = (const float4*)a_s;
#pragma unroll 2
    for (int f = 0; f < GF; f++) {
        float x0 = ctxp[(long long)f * SS + s0];
        float x1 = ctxp[(long long)f * SS + s1c];
        float4 a0 = ap[f * 4 + 0];
        float4 a1 = ap[f * 4 + 1];
        float4 a2 = ap[f * 4 + 2];
        float4 a3 = ap[f * 4 + 3];
        acc0[0]  += x0 * a0.x;  acc0[1]  += x0 * a0.y;  acc0[2]  += x0 * a0.z;  acc0[3]  += x0 * a0.w;
        acc0[4]  += x0 * a1.x;  acc0[5]  += x0 * a1.y;  acc0[6]  += x0 * a1.z;  acc0[7]  += x0 * a1.w;
        acc0[8]  += x0 * a2.x;  acc0[9]  += x0 * a2.y;  acc0[10] += x0 * a2.z;  acc0[11] += x0 * a2.w;
        acc0[12] += x0 * a3.x;  acc0[13] += x0 * a3.y;  acc0[14] += x0 * a3.z;  acc0[15] += x0 * a3.w;
        acc1[0]  += x1 * a0.x;  acc1[1]  += x1 * a0.y;  acc1[2]  += x1 * a0.z;  acc1[3]  += x1 * a0.w;
        acc1[4]  += x1 * a1.x;  acc1[5]  += x1 * a1.y;  acc1[6]  += x1 * a1.z;  acc1[7]  += x1 * a1.w;
        acc1[8]  += x1 * a2.x;  acc1[9]  += x1 * a2.y;  acc1[10] += x1 * a2.z;  acc1[11] += x1 * a2.w;
        acc1[12] += x1 * a3.x;  acc1[13] += x1 * a3.y;  acc1[14] += x1 * a3.z;  acc1[15] += x1 * a3.w;
    }

    float* adjp = g_adj + ((long long)(b * NGR + g)) * NMAX * SS;
#pragma unroll
    for (int n = 0; n < NMAX; n++) {
        adjp[(long long)n * SS + s0] = acc0[n];
        if (ok1) adjp[(long long)n * SS + s1] = acc1[n];
    }
}

// ---------------- K4: softmax -------------------------------------------------
__global__ void __launch_bounds__(256) softmax_k() {
    int n = blockIdx.x, g = blockIdx.y, b = blockIdx.z;
    if (n >= g_cnt[b]) return;
    float* row = g_adj + ((long long)((b * NGR + g) * NMAX + n)) * SS;
    int tid = threadIdx.x;
    __shared__ float red[8];

    float mx = -1e30f;
    for (int s = tid; s < SS; s += 256) mx = fmaxf(mx, row[s]);
#pragma unroll
    for (int o = 16; o > 0; o >>= 1) mx = fmaxf(mx, __shfl_xor_sync(0xffffffffu, mx, o));
    if ((tid & 31) == 0) red[tid >> 5] = mx;
    __syncthreads();
    if (tid < 32) {
        float v = (tid < 8) ? red[tid] : -1e30f;
#pragma unroll
        for (int o = 4; o > 0; o >>= 1) v = fmaxf(v, __shfl_xor_sync(0xffffffffu, v, o));
        if (tid == 0) red[0] = v;
    }
    __syncthreads();
    mx = red[0];
    __syncthreads();

    float sum = 0.f;
    for (int s = tid; s < SS; s += 256) {
        float e = __expf(row[s] - mx);
        row[s] = e;
        sum += e;
    }
#pragma unroll
    for (int o = 16; o > 0; o >>= 1) sum += __shfl_xor_sync(0xffffffffu, sum, o);
    if ((tid & 31) == 0) red[tid >> 5] = sum;
    __syncthreads();
    if (tid < 32) {
        float v = (tid < 8) ? red[tid] : 0.f;
#pragma unroll
        for (int o = 4; o > 0; o >>= 1) v += __shfl_xor_sync(0xffffffffu, v, o);
        if (tid == 0) red[0] = v;
    }
    __syncthreads();
    float inv = 1.f / red[0];
    for (int s = tid; s < SS; s += 256) row[s] *= inv;
}

// ---------------- K5: aggregate + residual -----------------------------------
__global__ void __launch_bounds__(256) aggregate_k() {
    int z = blockIdx.y;
    int b = z >> 2, g = z & 3;
    int f0 = blockIdx.x * 64;

    __shared__ __align__(16) float adjS[NMAX][33];
    __shared__ __align__(16) float ctxS[32][65];

    const float* adjp = g_adj + (long long)z * NMAX * SS;
    const float* ctxp = g_ctx + (long long)z * GF * SS;

    int tid = threadIdx.x;
    int fid = tid % 64, grp = tid / 64;
    float acc[4] = {0.f, 0.f, 0.f, 0.f};

    for (int s0 = 0; s0 < SS; s0 += 32) {
#pragma unroll
        for (int t = 0; t < 2; t++) {
            int lin = tid + 256 * t;
            int k = lin & 31, n = lin >> 5;
            adjS[n][k] = adjp[n * SS + s0 + k];
        }
#pragma unroll
        for (int t = 0; t < 8; t++) {
            int lin = tid + 256 * t;
            int k = lin & 31, i = lin >> 5;
            ctxS[k][i] = ctxp[(f0 + i) * SS + s0 + k];
        }
        __syncthreads();
#pragma unroll
        for (int k = 0; k < 32; k++) {
            float bv = ctxS[k][fid];
#pragma unroll
            for (int j = 0; j < 4; j++)
                acc[j] += adjS[grp * 4 + j][k] * bv;
        }
        __syncthreads();
    }

    int cnt = g_cnt[b], off = g_off[b];
#pragma unroll
    for (int j = 0; j < 4; j++) {
        int n = grp * 4 + j;
        if (n < cnt) {
            long long idx = (long long)(off + n) * (NGR * GF) + g * GF + f0 + fid;
            g_flat[idx] = acc[j] + g_emb[idx];
        }
    }
}

// ---------------- launch ----------------------------------------------------
extern "C" void kernel_launch(void* const* d_in, const int* in_sizes, int n_in,
                              void* d_out, int out_size) {
    const float* actor = (const float*)d_in[0];
    const float* fmap  = (const float*)d_in[1];
    const float* W_a   = (const float*)d_in[2];
    const float* b_a   = (const float*)d_in[3];
    const float* W_c   = (const float*)d_in[4];
    const float* b_c   = (const float*)d_in[5];
    const float* W_h   = (const float*)d_in[6];
    const void*  counts = d_in[7];
    int nbias = 0;
    for (int i = 0; i < n_in; i++) {
        switch (in_sizes[i]) {
            case TOT * IDIM:      actor = (const float*)d_in[i]; break;
            case NB * DIN * SS:   fmap  = (const float*)d_in[i]; break;
            case NGR * GF * IDIM: W_a   = (const float*)d_in[i]; break;
            case NGR * GF * DIN:  W_c   = (const float*)d_in[i]; break;
            case NGR * GF * GF:   W_h   = (const float*)d_in[i]; break;
            case NGR * GF:
                if (nbias++ == 0) b_a = (const float*)d_in[i];
                else              b_c = (const float*)d_in[i];
                break;
            case NB:              counts = d_in[i]; break;
            default: break;
        }
    }
    float* out = (float*)d_out;

    float* flat_p;
    cudaGetSymbolAddress((void**)&flat_p, g_flat);

    cudaFuncSetAttribute(ctx_mma_k, cudaFuncAttributeMaxDynamicSharedMemorySize,
                         SMEM_DYN);

    // ctx_mma_k at launch index 3 (ncu lands there)
    init_offsets_k<<<1, 32>>>(counts);                                    // 0
    split_w_k<<<(NGR * GF * CPAD + 255) / 256, 256>>>(W_c);               // 1
    split_fm_k<<<dim3(SPAD / 32, CPAD / 32, NB), dim3(32, 8)>>>(fmap);    // 2
    ctx_mma_k<<<dim3(STILES * MTILES, NB * NGR), 256, SMEM_DYN>>>(b_c);   // 3
    emb_part_k<<<dim3(5, 16, KSPLIT), 256>>>(actor, W_a);                 // 4
    emb_reduce_k<<<(TOT * NGR * GF + 255) / 256, 256>>>(b_a);             // 5
    adj_logits_k<<<dim3(4, NGR, NB), 256>>>();                            // 6
    softmax_k<<<dim3(NMAX, NGR, NB), 256>>>();                            // 7
    aggregate_k<<<dim3(4, 64), 256>>>();                                  // 8
    gemm_nt_k<<<dim3(5, 4, 4), 256>>>(flat_p, NGR * GF, GF,               // 9
                                      W_h, GF, (long long)GF * GF,
                                      nullptr,
                                      out, NGR * GF, GF,
                                      GF, 1);
}